// round 6
// baseline (speedup 1.0000x reference)
#include <cuda_runtime.h>
#include <cstdint>
#include <math.h>

#define B_  32
#define C_  256
#define HW_ 4096   // 64*64
#define N_  64

// Scratch (allocation-free rule: device globals)
__device__ float g_y[(size_t)B_ * C_ * HW_];   // forward-WHT of x (tf32-rounded)
__device__ float g_u[(size_t)B_ * C_ * HW_];   // pod-summed soft-thresholded conv output

// ---------------------------------------------------------------------------
// helpers
// ---------------------------------------------------------------------------
__device__ __forceinline__ float to_tf32(float f) {
    uint32_t r;
    asm("cvt.rna.tf32.f32 %0, %1;" : "=r"(r) : "f"(f));
    return __uint_as_float(r);
}

__device__ __forceinline__ float softthr(float a, float t) {
    float m = fmaxf(fabsf(a) - t, 0.0f);
    return copysignf(m, a);
}

__device__ __forceinline__ void mma_tf32(float* c, const uint32_t* a, const uint32_t* b) {
    asm volatile(
        "mma.sync.aligned.m16n8k8.row.col.f32.tf32.tf32.f32 "
        "{%0,%1,%2,%3}, {%4,%5,%6,%7}, {%8,%9}, {%0,%1,%2,%3};\n"
        : "+f"(c[0]), "+f"(c[1]), "+f"(c[2]), "+f"(c[3])
        : "r"(a[0]), "r"(a[1]), "r"(a[2]), "r"(a[3]), "r"(b[0]), "r"(b[1]));
}

// 6-stage butterfly WHT along rows (w axis), 64x64 plane in smem, 256 threads
__device__ __forceinline__ void wht_rows(float* sm, int t) {
#pragma unroll
    for (int s = 0; s < 6; ++s) {
        const int bit = 1 << s;
#pragma unroll
        for (int r = 0; r < 8; ++r) {
            int pp  = r * 256 + t;        // 2048 butterfly pairs
            int row = pp >> 5;            // 64 rows
            int j   = pp & 31;            // 32 pairs per row
            int i0  = ((j >> s) << (s + 1)) | (j & (bit - 1));
            float* p = sm + row * 64 + i0;
            float a = p[0], c = p[bit];
            p[0]   = a + c;
            p[bit] = a - c;
        }
        __syncthreads();
    }
}

// 6-stage butterfly WHT along columns (h axis)
__device__ __forceinline__ void wht_cols(float* sm, int t) {
#pragma unroll
    for (int s = 0; s < 6; ++s) {
        const int bit = 1 << s;
#pragma unroll
        for (int r = 0; r < 8; ++r) {
            int pp  = r * 256 + t;
            int col = pp & 63;            // 64 columns
            int j   = pp >> 6;            // 32 pairs per column
            int i0  = ((j >> s) << (s + 1)) | (j & (bit - 1));
            float* p = sm + i0 * 64 + col;
            float a = p[0], c = p[bit * 64];
            p[0]        = a + c;
            p[bit * 64] = a - c;
        }
        __syncthreads();
    }
}

// ---------------------------------------------------------------------------
// Kernel 1: y = WHT2D(x) per (b,c) plane, stored tf32-rounded
// ---------------------------------------------------------------------------
__global__ __launch_bounds__(256)
void wht_fwd_kernel(const float* __restrict__ x) {
    __shared__ float sm[64 * 64];
    const size_t base = (size_t)blockIdx.x * HW_;
    const int t = threadIdx.x;

    const float4* src = reinterpret_cast<const float4*>(x + base);
#pragma unroll
    for (int i = 0; i < 4; ++i)
        reinterpret_cast<float4*>(sm)[t + i * 256] = src[t + i * 256];
    __syncthreads();

    wht_rows(sm, t);
    wht_cols(sm, t);

    float4* dst = reinterpret_cast<float4*>(g_y + base);
#pragma unroll
    for (int i = 0; i < 4; ++i) {
        float4 vv = reinterpret_cast<float4*>(sm)[t + i * 256];
        vv.x = to_tf32(vv.x); vv.y = to_tf32(vv.y);
        vv.z = to_tf32(vv.z); vv.w = to_tf32(vv.w);
        dst[t + i * 256] = vv;
    }
}

// ---------------------------------------------------------------------------
// Kernel 2: per batch b: z_p = W_p @ Y_b  (M=64-tile of c_out, N=128-tile of hw,
// K=256), both pods share the Y tile; epilogue fuses v-scale, soft-threshold,
// pod sum -> g_u.
// grid: (HW/128, C/64, B), block: 256 (8 warps in 2x4, 32x32 per warp)
// ---------------------------------------------------------------------------
__global__ __launch_bounds__(256, 2)
void gemm_epi_kernel(const float* __restrict__ Wm, const float* __restrict__ v,
                     const float* __restrict__ T) {
    __shared__ float sW[2][64][36];    // [pod][m][k] pad->conflict-free frags
    __shared__ float sY[32][136];      // [k][n]      pad->conflict-free frags
    __shared__ float sVT[4][128];      // v0,v1,T0,T1 for this pixel tile

    const int t     = threadIdx.x;
    const int lane  = t & 31;
    const int wid   = t >> 5;
    const int warpM = wid >> 2;        // 0..1
    const int warpN = wid & 3;         // 0..3
    const int qrow  = lane >> 2;       // 0..7
    const int qcol  = lane & 3;        // 0..3

    const int nBase = blockIdx.x * 128;
    const int mBase = blockIdx.y * 64;
    const int b     = blockIdx.z;

    const float* Yb = g_y + (size_t)b * (C_ * HW_);

    // stage v/T tiles once
    {
        const float* srcs[4] = { v + nBase, v + HW_ + nBase, T + nBase, T + HW_ + nBase };
        for (int i = t; i < 512; i += 256)
            sVT[i >> 7][i & 127] = srcs[i >> 7][i & 127];
    }

    float acc[2][2][4][4];
#pragma unroll
    for (int p = 0; p < 2; ++p)
#pragma unroll
        for (int mt = 0; mt < 2; ++mt)
#pragma unroll
            for (int nt = 0; nt < 4; ++nt)
#pragma unroll
                for (int i = 0; i < 4; ++i) acc[p][mt][nt][i] = 0.0f;

    for (int k0 = 0; k0 < 256; k0 += 32) {
        __syncthreads();
        // load W tiles (64x32 per pod), tf32-round on the way in
#pragma unroll
        for (int p = 0; p < 2; ++p) {
#pragma unroll
            for (int i = 0; i < 2; ++i) {
                int idx = t + i * 256;          // 0..511 float4 slots
                int m   = idx >> 3;
                int k4  = idx & 7;
                float4 w4 = *reinterpret_cast<const float4*>(
                    Wm + (size_t)p * 65536 + (size_t)(mBase + m) * 256 + k0 + k4 * 4);
                w4.x = to_tf32(w4.x); w4.y = to_tf32(w4.y);
                w4.z = to_tf32(w4.z); w4.w = to_tf32(w4.w);
                *reinterpret_cast<float4*>(&sW[p][m][k4 * 4]) = w4;
            }
        }
        // load Y tile (32x128), already tf32-rounded
#pragma unroll
        for (int i = 0; i < 4; ++i) {
            int idx = t + i * 256;              // 0..1023 float4 slots
            int kr  = idx >> 5;
            int c4  = idx & 31;
            float4 yv = *reinterpret_cast<const float4*>(
                Yb + (size_t)(k0 + kr) * HW_ + nBase + c4 * 4);
            *reinterpret_cast<float4*>(&sY[kr][c4 * 4]) = yv;
        }
        __syncthreads();

#pragma unroll
        for (int kk = 0; kk < 4; ++kk) {
            uint32_t afr[2][2][4];
#pragma unroll
            for (int p = 0; p < 2; ++p)
#pragma unroll
                for (int mt = 0; mt < 2; ++mt) {
                    const float* ab = &sW[p][warpM * 32 + mt * 16 + qrow][kk * 8 + qcol];
                    afr[p][mt][0] = __float_as_uint(ab[0]);
                    afr[p][mt][1] = __float_as_uint(ab[8 * 36]);
                    afr[p][mt][2] = __float_as_uint(ab[4]);
                    afr[p][mt][3] = __float_as_uint(ab[8 * 36 + 4]);
                }
            uint32_t bfr[4][2];
#pragma unroll
            for (int nt = 0; nt < 4; ++nt) {
                const float* bb = &sY[kk * 8 + qcol][warpN * 32 + nt * 8 + qrow];
                bfr[nt][0] = __float_as_uint(bb[0]);
                bfr[nt][1] = __float_as_uint(bb[4 * 136]);
            }
#pragma unroll
            for (int p = 0; p < 2; ++p)
#pragma unroll
                for (int mt = 0; mt < 2; ++mt)
#pragma unroll
                    for (int nt = 0; nt < 4; ++nt)
                        mma_tf32(acc[p][mt][nt], afr[p][mt], bfr[nt]);
        }
    }

    // epilogue: u = ST(v0*z0,T0) + ST(v1*z1,T1)
    float* ub = g_u + ((size_t)b * C_ + mBase) * HW_ + nBase;
#pragma unroll
    for (int mt = 0; mt < 2; ++mt) {
#pragma unroll
        for (int nt = 0; nt < 4; ++nt) {
            int nc = warpN * 32 + nt * 8 + 2 * qcol;
            float v0a = sVT[0][nc], v0b = sVT[0][nc + 1];
            float v1a = sVT[1][nc], v1b = sVT[1][nc + 1];
            float t0a = sVT[2][nc], t0b = sVT[2][nc + 1];
            float t1a = sVT[3][nc], t1b = sVT[3][nc + 1];
            int r0 = warpM * 32 + mt * 16 + qrow;
            float* o0 = ub + (size_t)r0 * HW_ + nc;
            float* o1 = o0 + (size_t)8 * HW_;
            float2 w0, w1;
            w0.x = softthr(acc[0][mt][nt][0] * v0a, t0a) + softthr(acc[1][mt][nt][0] * v1a, t1a);
            w0.y = softthr(acc[0][mt][nt][1] * v0b, t0b) + softthr(acc[1][mt][nt][1] * v1b, t1b);
            w1.x = softthr(acc[0][mt][nt][2] * v0a, t0a) + softthr(acc[1][mt][nt][2] * v1a, t1a);
            w1.y = softthr(acc[0][mt][nt][3] * v0b, t0b) + softthr(acc[1][mt][nt][3] * v1b, t1b);
            *reinterpret_cast<float2*>(o0) = w0;
            *reinterpret_cast<float2*>(o1) = w1;
        }
    }
}

// ---------------------------------------------------------------------------
// Kernel 3: out = IWHT2D(u)/4096 + x
// ---------------------------------------------------------------------------
__global__ __launch_bounds__(256)
void wht_inv_kernel(const float* __restrict__ x, float* __restrict__ out) {
    __shared__ float sm[64 * 64];
    const size_t base = (size_t)blockIdx.x * HW_;
    const int t = threadIdx.x;

    const float4* src = reinterpret_cast<const float4*>(g_u + base);
#pragma unroll
    for (int i = 0; i < 4; ++i)
        reinterpret_cast<float4*>(sm)[t + i * 256] = src[t + i * 256];
    __syncthreads();

    wht_rows(sm, t);
    wht_cols(sm, t);

    const float scale = 1.0f / 4096.0f;
    const float4* xs = reinterpret_cast<const float4*>(x + base);
    float4* dst = reinterpret_cast<float4*>(out + base);
#pragma unroll
    for (int i = 0; i < 4; ++i) {
        float4 vv = reinterpret_cast<float4*>(sm)[t + i * 256];
        float4 xv = xs[t + i * 256];
        vv.x = fmaf(vv.x, scale, xv.x);
        vv.y = fmaf(vv.y, scale, xv.y);
        vv.z = fmaf(vv.z, scale, xv.z);
        vv.w = fmaf(vv.w, scale, xv.w);
        dst[t + i * 256] = vv;
    }
}

// ---------------------------------------------------------------------------
extern "C" void kernel_launch(void* const* d_in, const int* in_sizes, int n_in,
                              void* d_out, int out_size) {
    const float* x = (const float*)d_in[0];
    const float* v = (const float*)d_in[1];
    const float* W = (const float*)d_in[2];
    const float* T = (const float*)d_in[3];
    float* out = (float*)d_out;

    wht_fwd_kernel<<<B_ * C_, 256>>>(x);
    gemm_epi_kernel<<<dim3(HW_ / 128, C_ / 64, B_), 256>>>(W, v, T);
    wht_inv_kernel<<<B_ * C_, 256>>>(x, out);
}